// round 17
// baseline (speedup 1.0000x reference)
#include <cuda_runtime.h>
#include <math.h>

#define NB 40
#define NBINS 20
#define TPB 256
#define GRID (148 * 5 * 4)    // 5 CTAs/SM (40KB smem each), 4 waves
#define NACC 40               // g_acc[0..19] = A~_j (no kappa), [20..39] = D~_j

#define CNT_INC (1u << 24)
#define SUM_MASK 0xFFFFFFu
#define DS_SCALE 16384.0f     // 2^14
#define DS_INV (1.0f / 16384.0f)
#define DS_BIAS 32768         // 2^15 per element

__device__ double g_acc[NACC];
__device__ unsigned int g_count;

__device__ __forceinline__ float wred_f(float v) {
#pragma unroll
    for (int off = 16; off; off >>= 1)
        v += __shfl_down_sync(0xffffffffu, v, off);
    return v;
}

__global__ void __launch_bounds__(TPB, 5)
ace_priv_kernel(const float* __restrict__ preds,
                const float* __restrict__ targs,
                int n, float* __restrict__ out, int out_size) {
    // hist[b][tid]: thread-private column -> NO atomics, bank(tid) conflict-free.
    __shared__ unsigned int hist[NB * TPB];
    __shared__ float sBc[NB], sBd[NB];       // per-CTA bin totals
    __shared__ float smA[NBINS], smD[NBINS];

    const int tid = threadIdx.x;
    const int lane = tid & 31;

#pragma unroll
    for (int k = 0; k < NB; k++) hist[k * TPB + tid] = 0u;
    if (tid < NB) { sBc[tid] = 0.0f; sBd[tid] = 0.0f; }
    if (tid < NBINS) { smA[tid] = 0.0f; smD[tid] = 0.0f; }
    __syncthreads();

    // ---- main loop: per element = LDS + IADD + STS into private column ----
    const int n4 = n >> 2;
    const float4* p4 = (const float4*)preds;
    const float4* t4 = (const float4*)targs;
    const int stride = GRID * TPB;
    int g = blockIdx.x * TPB + tid;

    if (g < n4) {
        float4 pv = p4[g];
        float4 tv = t4[g];
        while (1) {
            int gn = g + stride;
            bool more = (gn < n4);
            float4 pn, tn;
            if (more) { pn = p4[gn]; tn = t4[gn]; }   // 1-ahead prefetch

#pragma unroll
            for (int e = 0; e < 4; e++) {
                float p = (e == 0) ? pv.x : (e == 1) ? pv.y : (e == 2) ? pv.z : pv.w;
                float t = (e == 0) ? tv.x : (e == 1) ? tv.y : (e == 2) ? tv.z : tv.w;
                int b = (int)(p * (float)NB);
                b = min(max(b, 0), NB - 1);
                int ds = __float2int_rn((p - t) * DS_SCALE);
                unsigned int inc = CNT_INC + (unsigned int)(ds + DS_BIAS);
                int idx = b * TPB + tid;
                hist[idx] += inc;                     // private: plain RMW
            }

            if (!more) break;
            pv = pn; tv = tn; g = gn;
        }
    }

    // ---- scalar tail (n % 4): CTA 0 ----
    {
        int base4 = n4 << 2;
        int rem = n - base4;
        if (blockIdx.x == 0 && tid < rem) {
            float p = preds[base4 + tid];
            float t = targs[base4 + tid];
            int b = min(max((int)(p * (float)NB), 0), NB - 1);
            int ds = __float2int_rn((p - t) * DS_SCALE);
            hist[b * TPB + tid] += CNT_INC + (unsigned int)(ds + DS_BIAS);
        }
    }
    __syncthreads();

    // ---- stage 1: reduce 256 columns -> per-CTA bin totals ----
#pragma unroll
    for (int b = 0; b < NB; b++) {
        unsigned int v = hist[b * TPB + tid];
        float cnt = (float)(v >> 24);
        float Dv = ((float)(int)((v & SUM_MASK) - ((v >> 24) << 15))) * DS_INV;
        cnt = wred_f(cnt);
        Dv = wred_f(Dv);
        if (lane == 0) { atomicAdd(&sBc[b], cnt); atomicAdd(&sBd[b], Dv); }
    }
    __syncthreads();

    // ---- stage 2: fold NB bin totals into 40 moments (thread b < NB) ----
    if (tid < NB) {
        float cnt = sBc[tid];
        float Dv = sBd[tid];
        float cb = ((float)tid + 0.5f) * (1.0f / (float)NB);
        float w   = __expf(-10.0f * cb * cb);        // base_b (kappa_j at finalize)
        float rho = __expf(cb * (20.0f / 19.0f));
#pragma unroll
        for (int j = 0; j < NBINS; j++) {
            atomicAdd(&smA[j], w * cnt);
            atomicAdd(&smD[j], w * Dv);
            w *= rho;
        }
    }
    __syncthreads();

    if (tid < NACC) {
        double v = (tid < NBINS) ? (double)smA[tid] : (double)smD[tid - NBINS];
        atomicAdd(&g_acc[tid], v);
    }
    __syncthreads();

    // ---- last CTA finalizes ----
    __shared__ unsigned int s_is_last;
    if (tid == 0) {
        __threadfence();
        unsigned int old = atomicAdd(&g_count, 1u);
        s_is_last = (old == gridDim.x - 1) ? 1u : 0u;
    }
    __syncthreads();

    if (s_is_last) {
        __shared__ double sloss[NBINS];
        if (tid < NBINS) {
            __threadfence();
            double Aj = atomicAdd(&g_acc[tid], 0.0);
            double Dj = atomicAdd(&g_acc[NBINS + tid], 0.0);
            double cj = (double)tid / 19.0;
            double kappa = exp(-10.0 * cj * cj);
            double ws = kappa * Aj;
            sloss[tid] = (ws != 0.0) ? fabs(kappa * Dj) / (ws + 1e-8) : 0.0;
        }
        __syncthreads();
        if (tid == 0) {
            double loss = 0.0;
            for (int j = 0; j < NBINS; j++) loss += sloss[j];
            float res = (float)(loss / NBINS);
            for (int i = 0; i < out_size; i++) out[i] = res;
            for (int k = 0; k < NACC; k++) g_acc[k] = 0.0;
            g_count = 0u;
            __threadfence();
        }
    }
}

extern "C" void kernel_launch(void* const* d_in, const int* in_sizes, int n_in,
                              void* d_out, int out_size) {
    const float* preds = (const float*)d_in[0];
    const float* targs = (const float*)d_in[1];
    int n = in_sizes[0];
    ace_priv_kernel<<<GRID, TPB>>>(preds, targs, n, (float*)d_out, out_size);
}